// round 10
// baseline (speedup 1.0000x reference)
#include <cuda_runtime.h>
#include <cuda_fp16.h>
#include <cstdint>

// ---------------------------------------------------------------------------
// Problem constants
// ---------------------------------------------------------------------------
constexpr int kE = 32, kD = 2048, kF = 768, kT = 2048;
constexpr int k2F = 2 * kF;                       // 1536

constexpr int BM = 128, BN = 128, BK = 64;        // fp16: BK=64 (4 k16-steps)
constexpr int STAGES = 3;
constexpr int NTHREADS = 256;                     // 8 warps, 2(m) x 4(n), warp 64x32

// smem stage: A 128x64 halves (128B rows, swizzled) = 16KB; B 64x128 halves
// (256B rows, per-128B-half swizzled) = 16KB.
constexpr int A_BYTES = BM * BK * 2;              // 16384
constexpr int B_BYTES = BK * BN * 2;              // 16384
constexpr int STAGE_BYTES = A_BYTES + B_BYTES;    // 32768
constexpr int SMEM_BYTES = STAGES * STAGE_BYTES;  // 98304 -> 2 CTA/SM (196KB)

// Scratch (device globals; uint4 arrays for 16B alignment)
__device__ uint4 g_Xh   [(size_t)kT * kD / 8];         // X fp16
__device__ uint4 g_Wguh [(size_t)kE * kD * k2F / 8];   // Wgu fp16
__device__ uint4 g_Wdh  [(size_t)kE * kF * kD / 8];    // Wd fp16
__device__ uint4 g_gatedh[(size_t)kE * kT * kF / 8];   // act output fp16
__device__ float g_gateup[(size_t)kE * kT * k2F];      // raw gate_up fp32
__device__ float g_part  [(size_t)kT * kD];            // split-K partial

// ---------------------------------------------------------------------------
// helpers
// ---------------------------------------------------------------------------
__device__ __forceinline__ uint32_t smem_u32(const void* p) {
    uint32_t a;
    asm("{ .reg .u64 t; cvta.to.shared.u64 t, %1; cvt.u32.u64 %0, t; }"
        : "=r"(a) : "l"(p));
    return a;
}
__device__ __forceinline__ void cp16(uint32_t saddr, const void* g) {
    asm volatile("cp.async.cg.shared.global [%0], [%1], 16;" :: "r"(saddr), "l"(g));
}
#define CP_COMMIT() asm volatile("cp.async.commit_group;" ::: "memory")
#define CP_WAIT1()  asm volatile("cp.async.wait_group 1;" ::: "memory")

__device__ __forceinline__ void ldsm4(uint32_t* r, uint32_t addr) {
    asm volatile("ldmatrix.sync.aligned.m8n8.x4.shared.b16 {%0,%1,%2,%3}, [%4];"
        : "=r"(r[0]), "=r"(r[1]), "=r"(r[2]), "=r"(r[3]) : "r"(addr));
}
__device__ __forceinline__ void ldsm4t(uint32_t* r, uint32_t addr) {
    asm volatile("ldmatrix.sync.aligned.m8n8.x4.trans.shared.b16 {%0,%1,%2,%3}, [%4];"
        : "=r"(r[0]), "=r"(r[1]), "=r"(r[2]), "=r"(r[3]) : "r"(addr));
}
__device__ __forceinline__ void mma16(float* c, const uint32_t* a, const uint32_t* b) {
    asm volatile(
        "mma.sync.aligned.m16n8k16.row.col.f32.f16.f16.f32 "
        "{%0,%1,%2,%3}, {%4,%5,%6,%7}, {%8,%9}, {%0,%1,%2,%3};"
        : "+f"(c[0]), "+f"(c[1]), "+f"(c[2]), "+f"(c[3])
        : "r"(a[0]), "r"(a[1]), "r"(a[2]), "r"(a[3]), "r"(b[0]), "r"(b[1]));
}

__device__ __forceinline__ uint32_t pack2(float x, float y) {
    __half2 h = __floats2half2_rn(x, y);
    return *reinterpret_cast<uint32_t*>(&h);
}

// ---------------------------------------------------------------------------
// Per-thread fragment addressing (precomputed outside K loop)
// A tile: [BM][64] halves, 128B rows, unit (16B) swizzle u^=(row&7).
// B tile: [BK][128] halves, 256B rows, swizzle on each 128B half: inner^=(row&7).
// ---------------------------------------------------------------------------
struct Frag {
    int aRow[4];    // rA*128
    int aMask[4];   // rA&7
    int hi;         // lane>>4 (k+8 selector for A, n+8 selector for B)
    int bOff[2];    // lane-constant byte offset per n16 group
    int g, tig, wm, wn;
};

__device__ __forceinline__ Frag make_frag(int tid) {
    Frag f;
    const int l = tid & 31, wid = tid >> 5;
    f.wm = (wid >> 2) * 64;
    f.wn = (wid & 3) * 32;
    f.g = l >> 2; f.tig = l & 3;
    f.hi = l >> 4;
    const int low8 = l & 7, seg8 = (l >> 3) & 1;
#pragma unroll
    for (int mi = 0; mi < 4; ++mi) {
        const int rA = f.wm + 16 * mi + low8 + 8 * seg8;
        f.aRow[mi] = rA * 128;
        f.aMask[mi] = rA & 7;
    }
#pragma unroll
    for (int p = 0; p < 2; ++p) {
        const int uB = (f.wn >> 3) + 2 * p + f.hi;       // 16B unit within 256B row
        f.bOff[p] = (l & 15) * 256 + ((uB >> 3) << 7) + ((((uB & 7) ^ low8)) << 4);
    }
    return f;
}

__device__ __forceinline__ void compute_stage(uint32_t As, uint32_t Bs,
                                              const Frag& f, float c[4][4][4]) {
#pragma unroll
    for (int ks = 0; ks < 4; ++ks) {             // k16 steps; kk = 16*ks halves
        const int kkU = 2 * ks;                  // 16B units per 16 halves
        uint32_t a[4][4];
#pragma unroll
        for (int mi = 0; mi < 4; ++mi)
            ldsm4(a[mi], As + f.aRow[mi] + (((kkU + f.hi) ^ f.aMask[mi]) << 4));
        uint32_t rb[2][4];
#pragma unroll
        for (int p = 0; p < 2; ++p)
            ldsm4t(rb[p], Bs + (16 * ks) * 256 + f.bOff[p]);
#pragma unroll
        for (int mi = 0; mi < 4; ++mi)
#pragma unroll
            for (int p = 0; p < 2; ++p) {
                mma16(c[mi][2 * p + 0], a[mi], &rb[p][0]);
                mma16(c[mi][2 * p + 1], a[mi], &rb[p][2]);
            }
    }
}

// cp.async destination offsets (byte), swizzled
__device__ __forceinline__ uint32_t a_dst(int row, int u) {        // u 0..7
    return (uint32_t)(row * 128 + ((u ^ (row & 7)) << 4));
}
__device__ __forceinline__ uint32_t b_dst(int row, int u) {        // u 0..15
    return (uint32_t)(row * 256 + ((u >> 3) << 7) + ((((u & 7) ^ (row & 7))) << 4));
}

// ---------------------------------------------------------------------------
// Pre-pass: fp32 -> fp16 conversion (plain layout)
// ---------------------------------------------------------------------------
__device__ __forceinline__ void conv8(const float* src, uint4* dst) {
    const float4 a = *(const float4*)(src);
    const float4 b = *(const float4*)(src + 4);
    uint4 o;
    o.x = pack2(a.x, a.y); o.y = pack2(a.z, a.w);
    o.z = pack2(b.x, b.y); o.w = pack2(b.z, b.w);
    *dst = o;
}
__global__ __launch_bounds__(256) void prep_X(const float* __restrict__ X) {
    const size_t i = (size_t)blockIdx.x * 256 + threadIdx.x;
    conv8(X + i * 8, g_Xh + i);
}
__global__ __launch_bounds__(256) void prep_Wgu(const float* __restrict__ W) {
    const size_t i = (size_t)blockIdx.x * 256 + threadIdx.x;
    conv8(W + i * 8, g_Wguh + i);
}
__global__ __launch_bounds__(256) void prep_Wd(const float* __restrict__ W) {
    const size_t i = (size_t)blockIdx.x * 256 + threadIdx.x;
    conv8(W + i * 8, g_Wdh + i);
}

// ---------------------------------------------------------------------------
// GEMM1: g_gateup[e][t][n] = Xh[t][:] @ Wguh[e][:][n]
// grid (16, 12, 32), 256 threads, 32 K-iters of BK=64
// ---------------------------------------------------------------------------
__global__ __launch_bounds__(NTHREADS, 2)
void moe_gemm1() {
    extern __shared__ char smem[];
    const int tid = threadIdx.x;
    const int m0 = blockIdx.x * BM, n0 = blockIdx.y * BN, e = blockIdx.z;
    const uint32_t sb = smem_u32(smem);

    const __half* Xh = (const __half*)g_Xh;
    const __half* We = (const __half*)g_Wguh + (size_t)e * kD * k2F;

    // cp.async: A row = tid>>1 (128), units (tid&1)*4+q; B row = tid>>2 (64), units (tid&3)*4+q
    const int arow = tid >> 1, au = (tid & 1) * 4;
    const int brow = tid >> 2, bu = (tid & 3) * 4;
    const __half* gA = Xh + (size_t)(m0 + arow) * kD + au * 8;
    const __half* gB = We + (size_t)brow * k2F + n0 + bu * 8;

    uint32_t aD[4], bD[4];
#pragma unroll
    for (int q = 0; q < 4; ++q) {
        aD[q] = a_dst(arow, au + q);
        bD[q] = b_dst(brow, bu + q);
    }

    const Frag f = make_frag(tid);
    float c[4][4][4];
#pragma unroll
    for (int i = 0; i < 4; ++i)
#pragma unroll
        for (int j = 0; j < 4; ++j)
#pragma unroll
            for (int q = 0; q < 4; ++q) c[i][j][q] = 0.0f;

    constexpr int ITERS = kD / BK;   // 32

    auto issue = [&](int it) {
        const uint32_t st = sb + (it % STAGES) * STAGE_BYTES;
        const int k0 = it * BK;
#pragma unroll
        for (int q = 0; q < 4; ++q)
            cp16(st + aD[q], gA + k0 + q * 8);
#pragma unroll
        for (int q = 0; q < 4; ++q)
            cp16(st + A_BYTES + bD[q], gB + (size_t)k0 * k2F + q * 8);
    };

    issue(0); CP_COMMIT();
    issue(1); CP_COMMIT();

    for (int it = 0; it < ITERS; ++it) {
        CP_WAIT1();
        __syncthreads();
        if (it + 2 < ITERS) issue(it + 2);
        CP_COMMIT();
        const uint32_t st = sb + (it % STAGES) * STAGE_BYTES;
        compute_stage(st, st + A_BYTES, f, c);
        // single barrier/iter: issue(it+2) touches stage (it-1)%3, already drained
    }

    float* Cp = g_gateup + ((size_t)e * kT + m0) * k2F + n0;
#pragma unroll
    for (int mi = 0; mi < 4; ++mi)
#pragma unroll
        for (int nj = 0; nj < 4; ++nj) {
            const int r0 = f.wm + 16 * mi + f.g;
            const int cc = f.wn + 8 * nj + 2 * f.tig;
            *(float2*)(Cp + (size_t)r0 * k2F + cc) = make_float2(c[mi][nj][0], c[mi][nj][1]);
            *(float2*)(Cp + (size_t)(r0 + 8) * k2F + cc) = make_float2(c[mi][nj][2], c[mi][nj][3]);
        }
}

// ---------------------------------------------------------------------------
// Act: g_gatedh[e][t][f] = fp16(rw[t][e] * up * silu(gate))
// ---------------------------------------------------------------------------
__global__ __launch_bounds__(256)
void moe_act(const float* __restrict__ RW) {
    constexpr int NO = kF / 8;                         // 96 octets per (e,t)
    const size_t idx = (size_t)blockIdx.x * 256 + threadIdx.x;
    const int oct = (int)(idx % NO);
    const size_t rest = idx / NO;
    const int t = (int)(rest % kT);
    const int e = (int)(rest / kT);

    const float rw = RW[(size_t)t * kE + e];
    const float* base = g_gateup + ((size_t)e * kT + t) * k2F + oct * 8;
    const float4 g0 = *(const float4*)(base);
    const float4 g1 = *(const float4*)(base + 4);
    const float4 u0 = *(const float4*)(base + kF);
    const float4 u1 = *(const float4*)(base + kF + 4);

    const float gt[8] = { g0.x, g0.y, g0.z, g0.w, g1.x, g1.y, g1.z, g1.w };
    const float up[8] = { u0.x, u0.y, u0.z, u0.w, u1.x, u1.y, u1.z, u1.w };
    float o[8];
#pragma unroll
    for (int j = 0; j < 8; ++j)
        o[j] = rw * up[j] * (gt[j] / (1.0f + __expf(-gt[j])));

    uint4 ov;
    ov.x = pack2(o[0], o[1]); ov.y = pack2(o[2], o[3]);
    ov.z = pack2(o[4], o[5]); ov.w = pack2(o[6], o[7]);
    g_gatedh[((size_t)e * kT + t) * (kF / 8) + oct] = ov;
}

// ---------------------------------------------------------------------------
// GEMM2 (split-K over experts): z=0 -> experts [0,16) -> Out, z=1 -> g_part.
// grid (16, 16, 2), 256 threads, 192 K-iters of BK=64.
// ---------------------------------------------------------------------------
__global__ __launch_bounds__(NTHREADS, 2)
void moe_gemm2(float* __restrict__ Out) {
    extern __shared__ char smem[];
    const int tid = threadIdx.x;
    const int m0 = blockIdx.x * BM, n0 = blockIdx.y * BN;
    const int ez = blockIdx.z * (kE / 2);
    const uint32_t sb = smem_u32(smem);

    const __half* Ah = (const __half*)g_gatedh;
    const __half* Wh = (const __half*)g_Wdh;

    const int arow = tid >> 1, au = (tid & 1) * 4;
    const int brow = tid >> 2, bu = (tid & 3) * 4;

    uint32_t aD[4], bD[4];
#pragma unroll
    for (int q = 0; q < 4; ++q) {
        aD[q] = a_dst(arow, au + q);
        bD[q] = b_dst(brow, bu + q);
    }

    const Frag f = make_frag(tid);
    float c[4][4][4];
#pragma unroll
    for (int i = 0; i < 4; ++i)
#pragma unroll
        for (int j = 0; j < 4; ++j)
#pragma unroll
            for (int q = 0; q < 4; ++q) c[i][j][q] = 0.0f;

    constexpr int IPEX  = kF / BK;                 // 12
    constexpr int ITERS = (kE / 2) * IPEX;         // 192

    auto issue = [&](int it) {
        const uint32_t st = sb + (it % STAGES) * STAGE_BYTES;
        const int e   = ez + it / IPEX;
        const int kin = (it % IPEX) * BK;
        const __half* gA = Ah + ((size_t)e * kT + m0 + arow) * kF + kin + au * 8;
        const __half* gB = Wh + ((size_t)e * kF + kin + brow) * kD + n0 + bu * 8;
#pragma unroll
        for (int q = 0; q < 4; ++q)
            cp16(st + aD[q], gA + q * 8);
#pragma unroll
        for (int q = 0; q < 4; ++q)
            cp16(st + A_BYTES + bD[q], gB + q * 8);
    };

    issue(0); CP_COMMIT();
    issue(1); CP_COMMIT();

    for (int it = 0; it < ITERS; ++it) {
        CP_WAIT1();
        __syncthreads();
        if (it + 2 < ITERS) issue(it + 2);
        CP_COMMIT();
        const uint32_t st = sb + (it % STAGES) * STAGE_BYTES;
        compute_stage(st, st + A_BYTES, f, c);
    }

    float* Cp = (blockIdx.z == 0 ? Out : g_part) + (size_t)m0 * kD + n0;
#pragma unroll
    for (int mi = 0; mi < 4; ++mi)
#pragma unroll
        for (int nj = 0; nj < 4; ++nj) {
            const int r0 = f.wm + 16 * mi + f.g;
            const int cc = f.wn + 8 * nj + 2 * f.tig;
            *(float2*)(Cp + (size_t)r0 * kD + cc) = make_float2(c[mi][nj][0], c[mi][nj][1]);
            *(float2*)(Cp + (size_t)(r0 + 8) * kD + cc) = make_float2(c[mi][nj][2], c[mi][nj][3]);
        }
}

// Combine split-K halves: Out += g_part
__global__ __launch_bounds__(256)
void moe_add(float* __restrict__ Out) {
    const size_t i4 = ((size_t)blockIdx.x * 256 + threadIdx.x) * 4;
    const float4 a = *(const float4*)(Out + i4);
    const float4 b = *(const float4*)(g_part + i4);
    *(float4*)(Out + i4) = make_float4(a.x + b.x, a.y + b.y, a.z + b.z, a.w + b.w);
}

// ---------------------------------------------------------------------------
// kernel_launch
//   0: hidden_states fp32 [T,D]   1: routing_weights fp32 [T,E]
//   2: router_indices (unused)    3: gate_up_proj fp32 [E,D,2F]
//   4: down_proj fp32 [E,F,D]     out: fp32 [T,D]
// ---------------------------------------------------------------------------
extern "C" void kernel_launch(void* const* d_in, const int* in_sizes, int n_in,
                              void* d_out, int out_size)
{
    const float* X   = (const float*)d_in[0];
    const float* RW  = (const float*)d_in[1];
    const float* Wgu = (const float*)d_in[3];
    const float* Wdn = (const float*)d_in[4];
    float* Out = (float*)d_out;

    cudaFuncSetAttribute(moe_gemm1, cudaFuncAttributeMaxDynamicSharedMemorySize, SMEM_BYTES);
    cudaFuncSetAttribute(moe_gemm2, cudaFuncAttributeMaxDynamicSharedMemorySize, SMEM_BYTES);

    prep_X<<<(int)(((size_t)kT * kD / 8) / 256), 256>>>(X);                    // 2048
    prep_Wgu<<<(int)(((size_t)kE * kD * k2F / 8) / 256), 256>>>(Wgu);          // 49152
    prep_Wd<<<(int)(((size_t)kE * kF * kD / 8) / 256), 256>>>(Wdn);            // 24576

    moe_gemm1<<<dim3(kT / BM, k2F / BN, kE), NTHREADS, SMEM_BYTES>>>();        // (16,12,32)

    const int actBlocks = (int)(((size_t)kE * kT * (kF / 8)) / 256);           // 24576
    moe_act<<<actBlocks, 256>>>(RW);

    moe_gemm2<<<dim3(kT / BM, kD / BN, 2), NTHREADS, SMEM_BYTES>>>(Out);       // (16,16,2)
    moe_add<<<(int)(((size_t)kT * kD / 4) / 256), 256>>>(Out);                 // 4096
}

// round 11
// speedup vs baseline: 1.0178x; 1.0178x over previous
#include <cuda_runtime.h>
#include <cuda_fp16.h>
#include <cstdint>

// ---------------------------------------------------------------------------
// Problem constants
// ---------------------------------------------------------------------------
constexpr int kE = 32, kD = 2048, kF = 768, kT = 2048;
constexpr int k2F = 2 * kF;                       // 1536

constexpr int BM = 128, BN = 128, BK = 64;        // fp16: BK=64 (4 k16-steps)
constexpr int STAGES = 3;
constexpr int NTHREADS = 256;                     // 8 warps, 2(m) x 4(n), warp 64x32

constexpr int A_BYTES = BM * BK * 2;              // 16384
constexpr int B_BYTES = BK * BN * 2;              // 16384
constexpr int STAGE_BYTES = A_BYTES + B_BYTES;    // 32768
constexpr int SMEM_BYTES = STAGES * STAGE_BYTES;  // 98304 -> 2 CTA/SM

// Scratch (device globals; uint4 arrays for 16B alignment)
__device__ uint4 g_Xh    [(size_t)kT * kD / 8];        // X fp16
__device__ uint4 g_Wguh  [(size_t)kE * kD * k2F / 8];  // Wgu fp16, gate/up col-interleaved
__device__ uint4 g_Wdh   [(size_t)kE * kF * kD / 8];   // Wd fp16
__device__ uint4 g_gatedh[(size_t)kE * kT * kF / 8];   // rw*up*silu(gate), fp16
__device__ float g_part  [(size_t)kT * kD];            // split-K partial

// ---------------------------------------------------------------------------
// helpers
// ---------------------------------------------------------------------------
__device__ __forceinline__ uint32_t smem_u32(const void* p) {
    uint32_t a;
    asm("{ .reg .u64 t; cvta.to.shared.u64 t, %1; cvt.u32.u64 %0, t; }"
        : "=r"(a) : "l"(p));
    return a;
}
__device__ __forceinline__ void cp16(uint32_t saddr, const void* g) {
    asm volatile("cp.async.cg.shared.global [%0], [%1], 16;" :: "r"(saddr), "l"(g));
}
#define CP_COMMIT() asm volatile("cp.async.commit_group;" ::: "memory")
#define CP_WAIT1()  asm volatile("cp.async.wait_group 1;" ::: "memory")

__device__ __forceinline__ void ldsm4(uint32_t* r, uint32_t addr) {
    asm volatile("ldmatrix.sync.aligned.m8n8.x4.shared.b16 {%0,%1,%2,%3}, [%4];"
        : "=r"(r[0]), "=r"(r[1]), "=r"(r[2]), "=r"(r[3]) : "r"(addr));
}
__device__ __forceinline__ void ldsm4t(uint32_t* r, uint32_t addr) {
    asm volatile("ldmatrix.sync.aligned.m8n8.x4.trans.shared.b16 {%0,%1,%2,%3}, [%4];"
        : "=r"(r[0]), "=r"(r[1]), "=r"(r[2]), "=r"(r[3]) : "r"(addr));
}
__device__ __forceinline__ void mma16(float* c, const uint32_t* a, const uint32_t* b) {
    asm volatile(
        "mma.sync.aligned.m16n8k16.row.col.f32.f16.f16.f32 "
        "{%0,%1,%2,%3}, {%4,%5,%6,%7}, {%8,%9}, {%0,%1,%2,%3};"
        : "+f"(c[0]), "+f"(c[1]), "+f"(c[2]), "+f"(c[3])
        : "r"(a[0]), "r"(a[1]), "r"(a[2]), "r"(a[3]), "r"(b[0]), "r"(b[1]));
}

__device__ __forceinline__ uint32_t pack2(float x, float y) {
    __half2 h = __floats2half2_rn(x, y);
    return *reinterpret_cast<uint32_t*>(&h);
}

// ---------------------------------------------------------------------------
// Per-thread fragment addressing (precomputed outside K loop)
// A tile: [BM][64] halves, 128B rows, 16B-unit swizzle u^=(row&7).
// B tile: [BK][128] halves, 256B rows, swizzle per 128B half.
// ---------------------------------------------------------------------------
struct Frag {
    int aRow[4];
    int aMask[4];
    int hi;
    int bOff[2];
    int g, tig, wm, wn;
};

__device__ __forceinline__ Frag make_frag(int tid) {
    Frag f;
    const int l = tid & 31, wid = tid >> 5;
    f.wm = (wid >> 2) * 64;
    f.wn = (wid & 3) * 32;
    f.g = l >> 2; f.tig = l & 3;
    f.hi = l >> 4;
    const int low8 = l & 7, seg8 = (l >> 3) & 1;
#pragma unroll
    for (int mi = 0; mi < 4; ++mi) {
        const int rA = f.wm + 16 * mi + low8 + 8 * seg8;
        f.aRow[mi] = rA * 128;
        f.aMask[mi] = rA & 7;
    }
#pragma unroll
    for (int p = 0; p < 2; ++p) {
        const int uB = (f.wn >> 3) + 2 * p + f.hi;
        f.bOff[p] = (l & 15) * 256 + ((uB >> 3) << 7) + ((((uB & 7) ^ low8)) << 4);
    }
    return f;
}

__device__ __forceinline__ void compute_stage(uint32_t As, uint32_t Bs,
                                              const Frag& f, float c[4][4][4]) {
#pragma unroll
    for (int ks = 0; ks < 4; ++ks) {
        const int kkU = 2 * ks;
        uint32_t a[4][4];
#pragma unroll
        for (int mi = 0; mi < 4; ++mi)
            ldsm4(a[mi], As + f.aRow[mi] + (((kkU + f.hi) ^ f.aMask[mi]) << 4));
        uint32_t rb[2][4];
#pragma unroll
        for (int p = 0; p < 2; ++p)
            ldsm4t(rb[p], Bs + (16 * ks) * 256 + f.bOff[p]);
#pragma unroll
        for (int mi = 0; mi < 4; ++mi)
#pragma unroll
            for (int p = 0; p < 2; ++p) {
                mma16(c[mi][2 * p + 0], a[mi], &rb[p][0]);
                mma16(c[mi][2 * p + 1], a[mi], &rb[p][2]);
            }
    }
}

// cp.async destination offsets (byte), swizzled
__device__ __forceinline__ uint32_t a_dst(int row, int u) {        // u 0..7
    return (uint32_t)(row * 128 + ((u ^ (row & 7)) << 4));
}
__device__ __forceinline__ uint32_t b_dst(int row, int u) {        // u 0..15
    return (uint32_t)(row * 256 + ((u >> 3) << 7) + ((((u & 7) ^ (row & 7))) << 4));
}

// ---------------------------------------------------------------------------
// Pre-pass kernels
// ---------------------------------------------------------------------------
__device__ __forceinline__ void conv8(const float* src, uint4* dst) {
    const float4 a = *(const float4*)(src);
    const float4 b = *(const float4*)(src + 4);
    uint4 o;
    o.x = pack2(a.x, a.y); o.y = pack2(a.z, a.w);
    o.z = pack2(b.x, b.y); o.w = pack2(b.z, b.w);
    *dst = o;
}
__global__ __launch_bounds__(256) void prep_X(const float* __restrict__ X) {
    const size_t i = (size_t)blockIdx.x * 256 + threadIdx.x;
    conv8(X + i * 8, g_Xh + i);
}
// Wgu: interleave gate/up columns. Output col 2j = orig col j (gate),
// output col 2j+1 = orig col j+kF (up). One thread per 8 output cols.
__global__ __launch_bounds__(256) void prep_Wgu(const float* __restrict__ W) {
    const size_t i = (size_t)blockIdx.x * 256 + threadIdx.x;  // over E*D*2F/8
    constexpr int NG = k2F / 8;                               // 192 groups/row
    const int grp = (int)(i % NG);                            // output octet
    const size_t row = i / NG;                                // over E*D rows
    const float* src = W + row * k2F;
    const int j0 = grp * 4;                                   // 4 gate/up pairs
    const float4 gt = *(const float4*)(src + j0);
    const float4 up = *(const float4*)(src + kF + j0);
    uint4 o;
    o.x = pack2(gt.x, up.x); o.y = pack2(gt.y, up.y);
    o.z = pack2(gt.z, up.z); o.w = pack2(gt.w, up.w);
    g_Wguh[i] = o;
}
__global__ __launch_bounds__(256) void prep_Wd(const float* __restrict__ W) {
    const size_t i = (size_t)blockIdx.x * 256 + threadIdx.x;
    conv8(W + i * 8, g_Wdh + i);
}

// ---------------------------------------------------------------------------
// GEMM1 (fused): C = Xh @ Wguh (gate/up interleaved cols), epilogue computes
// g_gatedh[e][t][f] = fp16(rw[t][e] * up * silu(gate)).
// Fragment cols (cc, cc+1) = (gate_f, up_f) with f = wn/2 + 4*nj + tig.
// grid (16, 12, 32), 256 threads, 32 K-iters of BK=64.
// ---------------------------------------------------------------------------
__global__ __launch_bounds__(NTHREADS, 2)
void moe_gemm1(const float* __restrict__ RW) {
    extern __shared__ char smem[];
    const int tid = threadIdx.x;
    const int m0 = blockIdx.x * BM, n0 = blockIdx.y * BN, e = blockIdx.z;
    const uint32_t sb = smem_u32(smem);

    const __half* Xh = (const __half*)g_Xh;
    const __half* We = (const __half*)g_Wguh + (size_t)e * kD * k2F;

    const int arow = tid >> 1, au = (tid & 1) * 4;
    const int brow = tid >> 2, bu = (tid & 3) * 4;
    const __half* gA = Xh + (size_t)(m0 + arow) * kD + au * 8;
    const __half* gB = We + (size_t)brow * k2F + n0 + bu * 8;

    uint32_t aD[4], bD[4];
#pragma unroll
    for (int q = 0; q < 4; ++q) {
        aD[q] = a_dst(arow, au + q);
        bD[q] = b_dst(brow, bu + q);
    }

    const Frag f = make_frag(tid);
    float c[4][4][4];
#pragma unroll
    for (int i = 0; i < 4; ++i)
#pragma unroll
        for (int j = 0; j < 4; ++j)
#pragma unroll
            for (int q = 0; q < 4; ++q) c[i][j][q] = 0.0f;

    constexpr int ITERS = kD / BK;   // 32

    auto issue = [&](int it) {
        const uint32_t st = sb + (it % STAGES) * STAGE_BYTES;
        const int k0 = it * BK;
#pragma unroll
        for (int q = 0; q < 4; ++q)
            cp16(st + aD[q], gA + k0 + q * 8);
#pragma unroll
        for (int q = 0; q < 4; ++q)
            cp16(st + A_BYTES + bD[q], gB + (size_t)k0 * k2F + q * 8);
    };

    issue(0); CP_COMMIT();
    issue(1); CP_COMMIT();

    for (int it = 0; it < ITERS; ++it) {
        CP_WAIT1();
        __syncthreads();
        if (it + 2 < ITERS) issue(it + 2);
        CP_COMMIT();
        const uint32_t st = sb + (it % STAGES) * STAGE_BYTES;
        compute_stage(st, st + A_BYTES, f, c);
    }

    // Fused epilogue: silu + routing weight, fp16 store.
    const int f0 = n0 >> 1;                            // 64 f-cols per CTA
    __half* Gh = (__half*)g_gatedh;
#pragma unroll
    for (int mi = 0; mi < 4; ++mi) {
        const int r0 = m0 + f.wm + 16 * mi + f.g;
        const float rw0 = RW[(size_t)r0 * kE + e];
        const float rw1 = RW[(size_t)(r0 + 8) * kE + e];
        __half* o0 = Gh + ((size_t)e * kT + r0) * kF + f0;
        __half* o1 = o0 + (size_t)8 * kF;
#pragma unroll
        for (int nj = 0; nj < 4; ++nj) {
            const int fl = (f.wn >> 1) + 4 * nj + f.tig;
            const float gt0 = c[mi][nj][0], up0 = c[mi][nj][1];
            const float gt1 = c[mi][nj][2], up1 = c[mi][nj][3];
            o0[fl] = __float2half_rn(rw0 * up0 * (gt0 / (1.0f + __expf(-gt0))));
            o1[fl] = __float2half_rn(rw1 * up1 * (gt1 / (1.0f + __expf(-gt1))));
        }
    }
}

// ---------------------------------------------------------------------------
// GEMM2 (split-K over experts): z=0 -> experts [0,16) -> Out, z=1 -> g_part.
// grid (16, 16, 2), 256 threads, 192 K-iters of BK=64.
// ---------------------------------------------------------------------------
__global__ __launch_bounds__(NTHREADS, 2)
void moe_gemm2(float* __restrict__ Out) {
    extern __shared__ char smem[];
    const int tid = threadIdx.x;
    const int m0 = blockIdx.x * BM, n0 = blockIdx.y * BN;
    const int ez = blockIdx.z * (kE / 2);
    const uint32_t sb = smem_u32(smem);

    const __half* Ah = (const __half*)g_gatedh;
    const __half* Wh = (const __half*)g_Wdh;

    const int arow = tid >> 1, au = (tid & 1) * 4;
    const int brow = tid >> 2, bu = (tid & 3) * 4;

    uint32_t aD[4], bD[4];
#pragma unroll
    for (int q = 0; q < 4; ++q) {
        aD[q] = a_dst(arow, au + q);
        bD[q] = b_dst(brow, bu + q);
    }

    const Frag f = make_frag(tid);
    float c[4][4][4];
#pragma unroll
    for (int i = 0; i < 4; ++i)
#pragma unroll
        for (int j = 0; j < 4; ++j)
#pragma unroll
            for (int q = 0; q < 4; ++q) c[i][j][q] = 0.0f;

    constexpr int IPEX  = kF / BK;                 // 12
    constexpr int ITERS = (kE / 2) * IPEX;         // 192

    auto issue = [&](int it) {
        const uint32_t st = sb + (it % STAGES) * STAGE_BYTES;
        const int e   = ez + it / IPEX;
        const int kin = (it % IPEX) * BK;
        const __half* gA = Ah + ((size_t)e * kT + m0 + arow) * kF + kin + au * 8;
        const __half* gB = Wh + ((size_t)e * kF + kin + brow) * kD + n0 + bu * 8;
#pragma unroll
        for (int q = 0; q < 4; ++q)
            cp16(st + aD[q], gA + q * 8);
#pragma unroll
        for (int q = 0; q < 4; ++q)
            cp16(st + A_BYTES + bD[q], gB + q * 8);
    };

    issue(0); CP_COMMIT();
    issue(1); CP_COMMIT();

    for (int it = 0; it < ITERS; ++it) {
        CP_WAIT1();
        __syncthreads();
        if (it + 2 < ITERS) issue(it + 2);
        CP_COMMIT();
        const uint32_t st = sb + (it % STAGES) * STAGE_BYTES;
        compute_stage(st, st + A_BYTES, f, c);
    }

    float* Cp = (blockIdx.z == 0 ? Out : g_part) + (size_t)m0 * kD + n0;
#pragma unroll
    for (int mi = 0; mi < 4; ++mi)
#pragma unroll
        for (int nj = 0; nj < 4; ++nj) {
            const int r0 = f.wm + 16 * mi + f.g;
            const int cc = f.wn + 8 * nj + 2 * f.tig;
            *(float2*)(Cp + (size_t)r0 * kD + cc) = make_float2(c[mi][nj][0], c[mi][nj][1]);
            *(float2*)(Cp + (size_t)(r0 + 8) * kD + cc) = make_float2(c[mi][nj][2], c[mi][nj][3]);
        }
}

// Combine split-K halves: Out += g_part
__global__ __launch_bounds__(256)
void moe_add(float* __restrict__ Out) {
    const size_t i4 = ((size_t)blockIdx.x * 256 + threadIdx.x) * 4;
    const float4 a = *(const float4*)(Out + i4);
    const float4 b = *(const float4*)(g_part + i4);
    *(float4*)(Out + i4) = make_float4(a.x + b.x, a.y + b.y, a.z + b.z, a.w + b.w);
}

// ---------------------------------------------------------------------------
// kernel_launch
//   0: hidden_states fp32 [T,D]   1: routing_weights fp32 [T,E]
//   2: router_indices (unused)    3: gate_up_proj fp32 [E,D,2F]
//   4: down_proj fp32 [E,F,D]     out: fp32 [T,D]
// ---------------------------------------------------------------------------
extern "C" void kernel_launch(void* const* d_in, const int* in_sizes, int n_in,
                              void* d_out, int out_size)
{
    const float* X   = (const float*)d_in[0];
    const float* RW  = (const float*)d_in[1];
    const float* Wgu = (const float*)d_in[3];
    const float* Wdn = (const float*)d_in[4];
    float* Out = (float*)d_out;

    cudaFuncSetAttribute(moe_gemm1, cudaFuncAttributeMaxDynamicSharedMemorySize, SMEM_BYTES);
    cudaFuncSetAttribute(moe_gemm2, cudaFuncAttributeMaxDynamicSharedMemorySize, SMEM_BYTES);

    prep_X<<<(int)(((size_t)kT * kD / 8) / 256), 256>>>(X);                    // 2048
    prep_Wgu<<<(int)(((size_t)kE * kD * k2F / 8) / 256), 256>>>(Wgu);          // 49152
    prep_Wd<<<(int)(((size_t)kE * kF * kD / 8) / 256), 256>>>(Wdn);            // 24576

    moe_gemm1<<<dim3(kT / BM, k2F / BN, kE), NTHREADS, SMEM_BYTES>>>(RW);      // (16,12,32)

    moe_gemm2<<<dim3(kT / BM, kD / BN, 2), NTHREADS, SMEM_BYTES>>>(Out);       // (16,16,2)
    moe_add<<<(int)(((size_t)kT * kD / 4) / 256), 256>>>(Out);                 // 4096
}

// round 12
// speedup vs baseline: 1.0379x; 1.0197x over previous
#include <cuda_runtime.h>
#include <cuda_fp16.h>
#include <cstdint>

// ---------------------------------------------------------------------------
// Problem constants
// ---------------------------------------------------------------------------
constexpr int kE = 32, kD = 2048, kF = 768, kT = 2048;
constexpr int k2F = 2 * kF;                       // 1536

constexpr int BM = 128, BN = 128, BK = 64;        // fp16: BK=64 (4 k16-steps)
constexpr int STAGES = 3;
constexpr int NTHREADS = 256;                     // 8 warps, 2(m) x 4(n), warp 64x32

constexpr int A_BYTES = BM * BK * 2;              // 16384
constexpr int B_BYTES = BK * BN * 2;              // 16384
constexpr int STAGE_BYTES = A_BYTES + B_BYTES;    // 32768
constexpr int SMEM_BYTES = STAGES * STAGE_BYTES;  // 98304 -> 2 CTA/SM

// Scratch (device globals; uint4 arrays for 16B alignment)
__device__ uint4 g_Xh    [(size_t)kT * kD / 8];        // X fp16
__device__ uint4 g_Wguh  [(size_t)kE * kD * k2F / 8];  // Wgu fp16, gate/up col-interleaved
__device__ uint4 g_Wdh   [(size_t)kE * kF * kD / 8];   // Wd fp16
__device__ uint4 g_gatedh[(size_t)kE * kT * kF / 8];   // rw*up*silu(gate), fp16
__device__ float g_part  [(size_t)kT * kD];            // split-K partial

// ---------------------------------------------------------------------------
// helpers
// ---------------------------------------------------------------------------
__device__ __forceinline__ uint32_t smem_u32(const void* p) {
    uint32_t a;
    asm("{ .reg .u64 t; cvta.to.shared.u64 t, %1; cvt.u32.u64 %0, t; }"
        : "=r"(a) : "l"(p));
    return a;
}
__device__ __forceinline__ void cp16(uint32_t saddr, const void* g) {
    asm volatile("cp.async.cg.shared.global [%0], [%1], 16;" :: "r"(saddr), "l"(g));
}
#define CP_COMMIT() asm volatile("cp.async.commit_group;" ::: "memory")
#define CP_WAIT1()  asm volatile("cp.async.wait_group 1;" ::: "memory")

__device__ __forceinline__ void ldsm4(uint32_t* r, uint32_t addr) {
    asm volatile("ldmatrix.sync.aligned.m8n8.x4.shared.b16 {%0,%1,%2,%3}, [%4];"
        : "=r"(r[0]), "=r"(r[1]), "=r"(r[2]), "=r"(r[3]) : "r"(addr));
}
__device__ __forceinline__ void ldsm4t(uint32_t* r, uint32_t addr) {
    asm volatile("ldmatrix.sync.aligned.m8n8.x4.trans.shared.b16 {%0,%1,%2,%3}, [%4];"
        : "=r"(r[0]), "=r"(r[1]), "=r"(r[2]), "=r"(r[3]) : "r"(addr));
}
__device__ __forceinline__ void mma16(float* c, const uint32_t* a, const uint32_t* b) {
    asm volatile(
        "mma.sync.aligned.m16n8k16.row.col.f32.f16.f16.f32 "
        "{%0,%1,%2,%3}, {%4,%5,%6,%7}, {%8,%9}, {%0,%1,%2,%3};"
        : "+f"(c[0]), "+f"(c[1]), "+f"(c[2]), "+f"(c[3])
        : "r"(a[0]), "r"(a[1]), "r"(a[2]), "r"(a[3]), "r"(b[0]), "r"(b[1]));
}

__device__ __forceinline__ uint32_t pack2(float x, float y) {
    __half2 h = __floats2half2_rn(x, y);
    return *reinterpret_cast<uint32_t*>(&h);
}

// ---------------------------------------------------------------------------
// Per-thread fragment addressing (precomputed outside K loop)
// A tile: [BM][64] halves, 128B rows, 16B-unit swizzle u^=(row&7).
// B tile: [BK][128] halves, 256B rows, swizzle per 128B half.
// ---------------------------------------------------------------------------
struct Frag {
    int aRow[4];
    int aMask[4];
    int hi;
    int bOff[2];
    int g, tig, wm, wn;
};

__device__ __forceinline__ Frag make_frag(int tid) {
    Frag f;
    const int l = tid & 31, wid = tid >> 5;
    f.wm = (wid >> 2) * 64;
    f.wn = (wid & 3) * 32;
    f.g = l >> 2; f.tig = l & 3;
    f.hi = l >> 4;
    const int low8 = l & 7, seg8 = (l >> 3) & 1;
#pragma unroll
    for (int mi = 0; mi < 4; ++mi) {
        const int rA = f.wm + 16 * mi + low8 + 8 * seg8;
        f.aRow[mi] = rA * 128;
        f.aMask[mi] = rA & 7;
    }
#pragma unroll
    for (int p = 0; p < 2; ++p) {
        const int uB = (f.wn >> 3) + 2 * p + f.hi;
        f.bOff[p] = (l & 15) * 256 + ((uB >> 3) << 7) + ((((uB & 7) ^ low8)) << 4);
    }
    return f;
}

__device__ __forceinline__ void compute_stage(uint32_t As, uint32_t Bs,
                                              const Frag& f, float c[4][4][4]) {
#pragma unroll
    for (int ks = 0; ks < 4; ++ks) {
        const int kkU = 2 * ks;
        uint32_t a[4][4];
#pragma unroll
        for (int mi = 0; mi < 4; ++mi)
            ldsm4(a[mi], As + f.aRow[mi] + (((kkU + f.hi) ^ f.aMask[mi]) << 4));
        uint32_t rb[2][4];
#pragma unroll
        for (int p = 0; p < 2; ++p)
            ldsm4t(rb[p], Bs + (16 * ks) * 256 + f.bOff[p]);
#pragma unroll
        for (int mi = 0; mi < 4; ++mi)
#pragma unroll
            for (int p = 0; p < 2; ++p) {
                mma16(c[mi][2 * p + 0], a[mi], &rb[p][0]);
                mma16(c[mi][2 * p + 1], a[mi], &rb[p][2]);
            }
    }
}

// cp.async destination offsets (byte), swizzled
__device__ __forceinline__ uint32_t a_dst(int row, int u) {        // u 0..7
    return (uint32_t)(row * 128 + ((u ^ (row & 7)) << 4));
}
__device__ __forceinline__ uint32_t b_dst(int row, int u) {        // u 0..15
    return (uint32_t)(row * 256 + ((u >> 3) << 7) + ((((u & 7) ^ (row & 7))) << 4));
}

// ---------------------------------------------------------------------------
// Pre-pass kernels
// ---------------------------------------------------------------------------
__device__ __forceinline__ void conv8(const float* src, uint4* dst) {
    const float4 a = *(const float4*)(src);
    const float4 b = *(const float4*)(src + 4);
    uint4 o;
    o.x = pack2(a.x, a.y); o.y = pack2(a.z, a.w);
    o.z = pack2(b.x, b.y); o.w = pack2(b.z, b.w);
    *dst = o;
}
__global__ __launch_bounds__(256) void prep_X(const float* __restrict__ X) {
    const size_t i = (size_t)blockIdx.x * 256 + threadIdx.x;
    conv8(X + i * 8, g_Xh + i);
}
// Wgu: interleave gate/up columns. Output col 2j = orig col j (gate),
// output col 2j+1 = orig col j+kF (up).
__global__ __launch_bounds__(256) void prep_Wgu(const float* __restrict__ W) {
    const size_t i = (size_t)blockIdx.x * 256 + threadIdx.x;  // over E*D*2F/8
    constexpr int NG = k2F / 8;                               // 192 groups/row
    const int grp = (int)(i % NG);
    const size_t row = i / NG;
    const float* src = W + row * k2F;
    const int j0 = grp * 4;
    const float4 gt = *(const float4*)(src + j0);
    const float4 up = *(const float4*)(src + kF + j0);
    uint4 o;
    o.x = pack2(gt.x, up.x); o.y = pack2(gt.y, up.y);
    o.z = pack2(gt.z, up.z); o.w = pack2(gt.w, up.w);
    g_Wguh[i] = o;
}
__global__ __launch_bounds__(256) void prep_Wd(const float* __restrict__ W) {
    const size_t i = (size_t)blockIdx.x * 256 + threadIdx.x;
    conv8(W + i * 8, g_Wdh + i);
}

// ---------------------------------------------------------------------------
// GEMM1 (fused): C = Xh @ Wguh (gate/up interleaved cols); epilogue computes
// fp16(rw*up*silu(gate)), stages through smem, stores coalesced 16B chunks.
// grid (16, 12, 32), 256 threads, 32 K-iters of BK=64.
// ---------------------------------------------------------------------------
constexpr int EP_LD = 72;   // halves per staging row (144B; pad kills bank alias)

__global__ __launch_bounds__(NTHREADS, 2)
void moe_gemm1(const float* __restrict__ RW) {
    extern __shared__ char smem[];
    const int tid = threadIdx.x;
    const int m0 = blockIdx.x * BM, n0 = blockIdx.y * BN, e = blockIdx.z;
    const uint32_t sb = smem_u32(smem);

    const __half* Xh = (const __half*)g_Xh;
    const __half* We = (const __half*)g_Wguh + (size_t)e * kD * k2F;

    const int arow = tid >> 1, au = (tid & 1) * 4;
    const int brow = tid >> 2, bu = (tid & 3) * 4;
    const __half* gA = Xh + (size_t)(m0 + arow) * kD + au * 8;
    const __half* gB = We + (size_t)brow * k2F + n0 + bu * 8;

    uint32_t aD[4], bD[4];
#pragma unroll
    for (int q = 0; q < 4; ++q) {
        aD[q] = a_dst(arow, au + q);
        bD[q] = b_dst(brow, bu + q);
    }

    const Frag f = make_frag(tid);
    float c[4][4][4];
#pragma unroll
    for (int i = 0; i < 4; ++i)
#pragma unroll
        for (int j = 0; j < 4; ++j)
#pragma unroll
            for (int q = 0; q < 4; ++q) c[i][j][q] = 0.0f;

    constexpr int ITERS = kD / BK;   // 32

    auto issue = [&](int it) {
        const uint32_t st = sb + (it % STAGES) * STAGE_BYTES;
        const int k0 = it * BK;
#pragma unroll
        for (int q = 0; q < 4; ++q)
            cp16(st + aD[q], gA + k0 + q * 8);
#pragma unroll
        for (int q = 0; q < 4; ++q)
            cp16(st + A_BYTES + bD[q], gB + (size_t)k0 * k2F + q * 8);
    };

    issue(0); CP_COMMIT();
    issue(1); CP_COMMIT();

    for (int it = 0; it < ITERS; ++it) {
        CP_WAIT1();
        __syncthreads();
        if (it + 2 < ITERS) issue(it + 2);
        CP_COMMIT();
        const uint32_t st = sb + (it % STAGES) * STAGE_BYTES;
        compute_stage(st, st + A_BYTES, f, c);
    }

    // ---- Fused epilogue, smem-staged for coalesced stores ----
    __syncthreads();                         // all warps done reading pipeline smem
    __half* s_ep = (__half*)smem;            // [128 rows][EP_LD halves]
#pragma unroll
    for (int mi = 0; mi < 4; ++mi) {
        const int row0 = f.wm + 16 * mi + f.g;       // CTA-local rows
        const int row1 = row0 + 8;
        const float rw0 = RW[(size_t)(m0 + row0) * kE + e];
        const float rw1 = RW[(size_t)(m0 + row1) * kE + e];
#pragma unroll
        for (int nj = 0; nj < 4; ++nj) {
            const int fl = (f.wn >> 1) + 4 * nj + f.tig;
            const float gt0 = c[mi][nj][0], up0 = c[mi][nj][1];
            const float gt1 = c[mi][nj][2], up1 = c[mi][nj][3];
            s_ep[row0 * EP_LD + fl] =
                __float2half_rn(rw0 * up0 * (gt0 / (1.0f + __expf(-gt0))));
            s_ep[row1 * EP_LD + fl] =
                __float2half_rn(rw1 * up1 * (gt1 / (1.0f + __expf(-gt1))));
        }
    }
    __syncthreads();

    // Coalesced write: 2 threads per row, 32 halves (64B) each.
    const int erow = tid >> 1, eseg = (tid & 1) * 32;
    const int f0 = n0 >> 1;                                  // 64 f-cols per CTA
    const uint4* src = (const uint4*)(s_ep + erow * EP_LD + eseg);
    uint4* dst = (uint4*)((__half*)g_gatedh +
                          ((size_t)e * kT + m0 + erow) * kF + f0 + eseg);
#pragma unroll
    for (int q = 0; q < 4; ++q) dst[q] = src[q];
}

// ---------------------------------------------------------------------------
// GEMM2 (split-K over experts): z=0 -> experts [0,16) -> Out, z=1 -> g_part.
// grid (16, 16, 2), 256 threads, 192 K-iters of BK=64.
// ---------------------------------------------------------------------------
__global__ __launch_bounds__(NTHREADS, 2)
void moe_gemm2(float* __restrict__ Out) {
    extern __shared__ char smem[];
    const int tid = threadIdx.x;
    const int m0 = blockIdx.x * BM, n0 = blockIdx.y * BN;
    const int ez = blockIdx.z * (kE / 2);
    const uint32_t sb = smem_u32(smem);

    const __half* Ah = (const __half*)g_gatedh;
    const __half* Wh = (const __half*)g_Wdh;

    const int arow = tid >> 1, au = (tid & 1) * 4;
    const int brow = tid >> 2, bu = (tid & 3) * 4;

    uint32_t aD[4], bD[4];
#pragma unroll
    for (int q = 0; q < 4; ++q) {
        aD[q] = a_dst(arow, au + q);
        bD[q] = b_dst(brow, bu + q);
    }

    const Frag f = make_frag(tid);
    float c[4][4][4];
#pragma unroll
    for (int i = 0; i < 4; ++i)
#pragma unroll
        for (int j = 0; j < 4; ++j)
#pragma unroll
            for (int q = 0; q < 4; ++q) c[i][j][q] = 0.0f;

    constexpr int IPEX  = kF / BK;                 // 12
    constexpr int ITERS = (kE / 2) * IPEX;         // 192

    auto issue = [&](int it) {
        const uint32_t st = sb + (it % STAGES) * STAGE_BYTES;
        const int e   = ez + it / IPEX;
        const int kin = (it % IPEX) * BK;
        const __half* gA = Ah + ((size_t)e * kT + m0 + arow) * kF + kin + au * 8;
        const __half* gB = Wh + ((size_t)e * kF + kin + brow) * kD + n0 + bu * 8;
#pragma unroll
        for (int q = 0; q < 4; ++q)
            cp16(st + aD[q], gA + q * 8);
#pragma unroll
        for (int q = 0; q < 4; ++q)
            cp16(st + A_BYTES + bD[q], gB + q * 8);
    };

    issue(0); CP_COMMIT();
    issue(1); CP_COMMIT();

    for (int it = 0; it < ITERS; ++it) {
        CP_WAIT1();
        __syncthreads();
        if (it + 2 < ITERS) issue(it + 2);
        CP_COMMIT();
        const uint32_t st = sb + (it % STAGES) * STAGE_BYTES;
        compute_stage(st, st + A_BYTES, f, c);
    }

    float* Cp = (blockIdx.z == 0 ? Out : g_part) + (size_t)m0 * kD + n0;
#pragma unroll
    for (int mi = 0; mi < 4; ++mi)
#pragma unroll
        for (int nj = 0; nj < 4; ++nj) {
            const int r0 = f.wm + 16 * mi + f.g;
            const int cc = f.wn + 8 * nj + 2 * f.tig;
            *(float2*)(Cp + (size_t)r0 * kD + cc) = make_float2(c[mi][nj][0], c[mi][nj][1]);
            *(float2*)(Cp + (size_t)(r0 + 8) * kD + cc) = make_float2(c[mi][nj][2], c[mi][nj][3]);
        }
}

// Combine split-K halves: Out += g_part
__global__ __launch_bounds__(256)
void moe_add(float* __restrict__ Out) {
    const size_t i4 = ((size_t)blockIdx.x * 256 + threadIdx.x) * 4;
    const float4 a = *(const float4*)(Out + i4);
    const float4 b = *(const float4*)(g_part + i4);
    *(float4*)(Out + i4) = make_float4(a.x + b.x, a.y + b.y, a.z + b.z, a.w + b.w);
}

// ---------------------------------------------------------------------------
// kernel_launch
//   0: hidden_states fp32 [T,D]   1: routing_weights fp32 [T,E]
//   2: router_indices (unused)    3: gate_up_proj fp32 [E,D,2F]
//   4: down_proj fp32 [E,F,D]     out: fp32 [T,D]
// ---------------------------------------------------------------------------
extern "C" void kernel_launch(void* const* d_in, const int* in_sizes, int n_in,
                              void* d_out, int out_size)
{
    const float* X   = (const float*)d_in[0];
    const float* RW  = (const float*)d_in[1];
    const float* Wgu = (const float*)d_in[3];
    const float* Wdn = (const float*)d_in[4];
    float* Out = (float*)d_out;

    cudaFuncSetAttribute(moe_gemm1, cudaFuncAttributeMaxDynamicSharedMemorySize, SMEM_BYTES);
    cudaFuncSetAttribute(moe_gemm2, cudaFuncAttributeMaxDynamicSharedMemorySize, SMEM_BYTES);

    prep_X<<<(int)(((size_t)kT * kD / 8) / 256), 256>>>(X);                    // 2048
    prep_Wgu<<<(int)(((size_t)kE * kD * k2F / 8) / 256), 256>>>(Wgu);          // 49152
    prep_Wd<<<(int)(((size_t)kE * kF * kD / 8) / 256), 256>>>(Wdn);            // 24576

    moe_gemm1<<<dim3(kT / BM, k2F / BN, kE), NTHREADS, SMEM_BYTES>>>(RW);      // (16,12,32)

    moe_gemm2<<<dim3(kT / BM, kD / BN, 2), NTHREADS, SMEM_BYTES>>>(Out);       // (16,16,2)
    moe_add<<<(int)(((size_t)kT * kD / 4) / 256), 256>>>(Out);                 // 4096
}

// round 13
// speedup vs baseline: 1.0469x; 1.0087x over previous
#include <cuda_runtime.h>
#include <cuda_fp16.h>
#include <cstdint>

// ---------------------------------------------------------------------------
// Problem constants
// ---------------------------------------------------------------------------
constexpr int kE = 32, kD = 2048, kF = 768, kT = 2048;
constexpr int k2F = 2 * kF;                       // 1536

constexpr int BM = 128, BN = 128, BK = 64;        // fp16: BK=64 (4 k16-steps)
constexpr int STAGES = 3;
constexpr int NTHREADS = 256;                     // 8 warps, 2(m) x 4(n), warp 64x32

constexpr int A_BYTES = BM * BK * 2;              // 16384
constexpr int B_BYTES = BK * BN * 2;              // 16384
constexpr int STAGE_BYTES = A_BYTES + B_BYTES;    // 32768
constexpr int SMEM_BYTES = STAGES * STAGE_BYTES;  // 98304 -> 2 CTA/SM

// Scratch (device globals; uint4 arrays for 16B alignment)
__device__ uint4 g_Xh    [(size_t)kT * kD / 8];        // X fp16
__device__ uint4 g_Wguh  [(size_t)kE * kD * k2F / 8];  // Wgu fp16, gate/up col-interleaved
__device__ uint4 g_Wdh   [(size_t)kE * kF * kD / 8];   // Wd fp16
__device__ uint4 g_gatedh[(size_t)kE * kT * kF / 8];   // rw*up*silu(gate), fp16
__device__ float g_part  [(size_t)kT * kD];            // split-K partial

// ---------------------------------------------------------------------------
// helpers
// ---------------------------------------------------------------------------
__device__ __forceinline__ uint32_t smem_u32(const void* p) {
    uint32_t a;
    asm("{ .reg .u64 t; cvta.to.shared.u64 t, %1; cvt.u32.u64 %0, t; }"
        : "=r"(a) : "l"(p));
    return a;
}
__device__ __forceinline__ void cp16(uint32_t saddr, const void* g) {
    asm volatile("cp.async.cg.shared.global [%0], [%1], 16;" :: "r"(saddr), "l"(g));
}
#define CP_COMMIT() asm volatile("cp.async.commit_group;" ::: "memory")
#define CP_WAIT1()  asm volatile("cp.async.wait_group 1;" ::: "memory")

__device__ __forceinline__ void ldsm4(uint32_t* r, uint32_t addr) {
    asm volatile("ldmatrix.sync.aligned.m8n8.x4.shared.b16 {%0,%1,%2,%3}, [%4];"
        : "=r"(r[0]), "=r"(r[1]), "=r"(r[2]), "=r"(r[3]) : "r"(addr));
}
__device__ __forceinline__ void ldsm4t(uint32_t* r, uint32_t addr) {
    asm volatile("ldmatrix.sync.aligned.m8n8.x4.trans.shared.b16 {%0,%1,%2,%3}, [%4];"
        : "=r"(r[0]), "=r"(r[1]), "=r"(r[2]), "=r"(r[3]) : "r"(addr));
}
__device__ __forceinline__ void mma16(float* c, const uint32_t* a, const uint32_t* b) {
    asm volatile(
        "mma.sync.aligned.m16n8k16.row.col.f32.f16.f16.f32 "
        "{%0,%1,%2,%3}, {%4,%5,%6,%7}, {%8,%9}, {%0,%1,%2,%3};"
        : "+f"(c[0]), "+f"(c[1]), "+f"(c[2]), "+f"(c[3])
        : "r"(a[0]), "r"(a[1]), "r"(a[2]), "r"(a[3]), "r"(b[0]), "r"(b[1]));
}

__device__ __forceinline__ uint32_t pack2(float x, float y) {
    __half2 h = __floats2half2_rn(x, y);
    return *reinterpret_cast<uint32_t*>(&h);
}

// ---------------------------------------------------------------------------
// Per-thread fragment addressing (precomputed outside K loop)
// A tile: [BM][64] halves, 128B rows, 16B-unit swizzle u^=(row&7).
// B tile: [BK][128] halves, 256B rows, swizzle per 128B half.
// ---------------------------------------------------------------------------
struct Frag {
    int aRow[4];
    int aMask[4];
    int hi;
    int bOff[2];
    int g, tig, wm, wn;
};

__device__ __forceinline__ Frag make_frag(int tid) {
    Frag f;
    const int l = tid & 31, wid = tid >> 5;
    f.wm = (wid >> 2) * 64;
    f.wn = (wid & 3) * 32;
    f.g = l >> 2; f.tig = l & 3;
    f.hi = l >> 4;
    const int low8 = l & 7, seg8 = (l >> 3) & 1;
#pragma unroll
    for (int mi = 0; mi < 4; ++mi) {
        const int rA = f.wm + 16 * mi + low8 + 8 * seg8;
        f.aRow[mi] = rA * 128;
        f.aMask[mi] = rA & 7;
    }
#pragma unroll
    for (int p = 0; p < 2; ++p) {
        const int uB = (f.wn >> 3) + 2 * p + f.hi;
        f.bOff[p] = (l & 15) * 256 + ((uB >> 3) << 7) + ((((uB & 7) ^ low8)) << 4);
    }
    return f;
}

// Software-pipelined stage: fragments for k-step ks+1 are loaded BEFORE the
// MMAs of step ks, so LDSM latency hides under 16 independent MMA issues.
__device__ __forceinline__ void compute_stage(uint32_t As, uint32_t Bs,
                                              const Frag& f, float c[4][4][4]) {
    uint32_t a[2][4][4], rb[2][2][4];
#pragma unroll
    for (int mi = 0; mi < 4; ++mi)
        ldsm4(a[0][mi], As + f.aRow[mi] + ((f.hi ^ f.aMask[mi]) << 4));
#pragma unroll
    for (int p = 0; p < 2; ++p)
        ldsm4t(rb[0][p], Bs + f.bOff[p]);

#pragma unroll
    for (int ks = 0; ks < 4; ++ks) {
        const int cur = ks & 1, nxt = cur ^ 1;
        if (ks < 3) {
            const int kkU = 2 * (ks + 1);
#pragma unroll
            for (int mi = 0; mi < 4; ++mi)
                ldsm4(a[nxt][mi], As + f.aRow[mi] + (((kkU + f.hi) ^ f.aMask[mi]) << 4));
#pragma unroll
            for (int p = 0; p < 2; ++p)
                ldsm4t(rb[nxt][p], Bs + (16 * (ks + 1)) * 256 + f.bOff[p]);
        }
#pragma unroll
        for (int mi = 0; mi < 4; ++mi)
#pragma unroll
            for (int p = 0; p < 2; ++p) {
                mma16(c[mi][2 * p + 0], a[cur][mi], &rb[cur][p][0]);
                mma16(c[mi][2 * p + 1], a[cur][mi], &rb[cur][p][2]);
            }
    }
}

// cp.async destination offsets (byte), swizzled
__device__ __forceinline__ uint32_t a_dst(int row, int u) {        // u 0..7
    return (uint32_t)(row * 128 + ((u ^ (row & 7)) << 4));
}
__device__ __forceinline__ uint32_t b_dst(int row, int u) {        // u 0..15
    return (uint32_t)(row * 256 + ((u >> 3) << 7) + ((((u & 7) ^ (row & 7))) << 4));
}

// ---------------------------------------------------------------------------
// Pre-pass kernels
// ---------------------------------------------------------------------------
__device__ __forceinline__ void conv8(const float* src, uint4* dst) {
    const float4 a = *(const float4*)(src);
    const float4 b = *(const float4*)(src + 4);
    uint4 o;
    o.x = pack2(a.x, a.y); o.y = pack2(a.z, a.w);
    o.z = pack2(b.x, b.y); o.w = pack2(b.z, b.w);
    *dst = o;
}
__global__ __launch_bounds__(256) void prep_X(const float* __restrict__ X) {
    const size_t i = (size_t)blockIdx.x * 256 + threadIdx.x;
    conv8(X + i * 8, g_Xh + i);
}
// Wgu: interleave gate/up columns. Output col 2j = orig col j (gate),
// output col 2j+1 = orig col j+kF (up).
__global__ __launch_bounds__(256) void prep_Wgu(const float* __restrict__ W) {
    const size_t i = (size_t)blockIdx.x * 256 + threadIdx.x;  // over E*D*2F/8
    constexpr int NG = k2F / 8;                               // 192 groups/row
    const int grp = (int)(i % NG);
    const size_t row = i / NG;
    const float* src = W + row * k2F;
    const int j0 = grp * 4;
    const float4 gt = *(const float4*)(src + j0);
    const float4 up = *(const float4*)(src + kF + j0);
    uint4 o;
    o.x = pack2(gt.x, up.x); o.y = pack2(gt.y, up.y);
    o.z = pack2(gt.z, up.z); o.w = pack2(gt.w, up.w);
    g_Wguh[i] = o;
}
__global__ __launch_bounds__(256) void prep_Wd(const float* __restrict__ W) {
    const size_t i = (size_t)blockIdx.x * 256 + threadIdx.x;
    conv8(W + i * 8, g_Wdh + i);
}

// ---------------------------------------------------------------------------
// GEMM1 (fused): C = Xh @ Wguh (gate/up interleaved cols); epilogue computes
// fp16(rw*up*silu(gate)), stages through smem, stores coalesced 16B chunks.
// grid (16, 12, 32), 256 threads, 32 K-iters of BK=64.
// ---------------------------------------------------------------------------
constexpr int EP_LD = 72;   // halves per staging row (144B; pad kills bank alias)

__global__ __launch_bounds__(NTHREADS, 2)
void moe_gemm1(const float* __restrict__ RW) {
    extern __shared__ char smem[];
    const int tid = threadIdx.x;
    const int m0 = blockIdx.x * BM, n0 = blockIdx.y * BN, e = blockIdx.z;
    const uint32_t sb = smem_u32(smem);

    const __half* Xh = (const __half*)g_Xh;
    const __half* We = (const __half*)g_Wguh + (size_t)e * kD * k2F;

    const int arow = tid >> 1, au = (tid & 1) * 4;
    const int brow = tid >> 2, bu = (tid & 3) * 4;
    const __half* gA = Xh + (size_t)(m0 + arow) * kD + au * 8;
    const __half* gB = We + (size_t)brow * k2F + n0 + bu * 8;

    uint32_t aD[4], bD[4];
#pragma unroll
    for (int q = 0; q < 4; ++q) {
        aD[q] = a_dst(arow, au + q);
        bD[q] = b_dst(brow, bu + q);
    }

    const Frag f = make_frag(tid);
    float c[4][4][4];
#pragma unroll
    for (int i = 0; i < 4; ++i)
#pragma unroll
        for (int j = 0; j < 4; ++j)
#pragma unroll
            for (int q = 0; q < 4; ++q) c[i][j][q] = 0.0f;

    constexpr int ITERS = kD / BK;   // 32

    auto issue = [&](int it) {
        const uint32_t st = sb + (it % STAGES) * STAGE_BYTES;
        const int k0 = it * BK;
#pragma unroll
        for (int q = 0; q < 4; ++q)
            cp16(st + aD[q], gA + k0 + q * 8);
#pragma unroll
        for (int q = 0; q < 4; ++q)
            cp16(st + A_BYTES + bD[q], gB + (size_t)k0 * k2F + q * 8);
    };

    issue(0); CP_COMMIT();
    issue(1); CP_COMMIT();

    for (int it = 0; it < ITERS; ++it) {
        CP_WAIT1();
        __syncthreads();
        if (it + 2 < ITERS) issue(it + 2);
        CP_COMMIT();
        const uint32_t st = sb + (it % STAGES) * STAGE_BYTES;
        compute_stage(st, st + A_BYTES, f, c);
    }

    // ---- Fused epilogue, smem-staged for coalesced stores ----
    __syncthreads();
    __half* s_ep = (__half*)smem;            // [128 rows][EP_LD halves]
#pragma unroll
    for (int mi = 0; mi < 4; ++mi) {
        const int row0 = f.wm + 16 * mi + f.g;
        const int row1 = row0 + 8;
        const float rw0 = RW[(size_t)(m0 + row0) * kE + e];
        const float rw1 = RW[(size_t)(m0 + row1) * kE + e];
#pragma unroll
        for (int nj = 0; nj < 4; ++nj) {
            const int fl = (f.wn >> 1) + 4 * nj + f.tig;
            const float gt0 = c[mi][nj][0], up0 = c[mi][nj][1];
            const float gt1 = c[mi][nj][2], up1 = c[mi][nj][3];
            s_ep[row0 * EP_LD + fl] =
                __float2half_rn(rw0 * up0 * (gt0 / (1.0f + __expf(-gt0))));
            s_ep[row1 * EP_LD + fl] =
                __float2half_rn(rw1 * up1 * (gt1 / (1.0f + __expf(-gt1))));
        }
    }
    __syncthreads();

    const int erow = tid >> 1, eseg = (tid & 1) * 32;
    const int f0 = n0 >> 1;
    const uint4* src = (const uint4*)(s_ep + erow * EP_LD + eseg);
    uint4* dst = (uint4*)((__half*)g_gatedh +
                          ((size_t)e * kT + m0 + erow) * kF + f0 + eseg);
#pragma unroll
    for (int q = 0; q < 4; ++q) dst[q] = src[q];
}

// ---------------------------------------------------------------------------
// GEMM2 (split-K over experts): z=0 -> experts [0,16) -> Out, z=1 -> g_part.
// grid (16, 16, 2), 256 threads, 192 K-iters of BK=64.
// ---------------------------------------------------------------------------
__global__ __launch_bounds__(NTHREADS, 2)
void moe_gemm2(float* __restrict__ Out) {
    extern __shared__ char smem[];
    const int tid = threadIdx.x;
    const int m0 = blockIdx.x * BM, n0 = blockIdx.y * BN;
    const int ez = blockIdx.z * (kE / 2);
    const uint32_t sb = smem_u32(smem);

    const __half* Ah = (const __half*)g_gatedh;
    const __half* Wh = (const __half*)g_Wdh;

    const int arow = tid >> 1, au = (tid & 1) * 4;
    const int brow = tid >> 2, bu = (tid & 3) * 4;

    uint32_t aD[4], bD[4];
#pragma unroll
    for (int q = 0; q < 4; ++q) {
        aD[q] = a_dst(arow, au + q);
        bD[q] = b_dst(brow, bu + q);
    }

    const Frag f = make_frag(tid);
    float c[4][4][4];
#pragma unroll
    for (int i = 0; i < 4; ++i)
#pragma unroll
        for (int j = 0; j < 4; ++j)
#pragma unroll
            for (int q = 0; q < 4; ++q) c[i][j][q] = 0.0f;

    constexpr int IPEX  = kF / BK;                 // 12
    constexpr int ITERS = (kE / 2) * IPEX;         // 192

    auto issue = [&](int it) {
        const uint32_t st = sb + (it % STAGES) * STAGE_BYTES;
        const int e   = ez + it / IPEX;
        const int kin = (it % IPEX) * BK;
        const __half* gA = Ah + ((size_t)e * kT + m0 + arow) * kF + kin + au * 8;
        const __half* gB = Wh + ((size_t)e * kF + kin + brow) * kD + n0 + bu * 8;
#pragma unroll
        for (int q = 0; q < 4; ++q)
            cp16(st + aD[q], gA + q * 8);
#pragma unroll
        for (int q = 0; q < 4; ++q)
            cp16(st + A_BYTES + bD[q], gB + q * 8);
    };

    issue(0); CP_COMMIT();
    issue(1); CP_COMMIT();

    for (int it = 0; it < ITERS; ++it) {
        CP_WAIT1();
        __syncthreads();
        if (it + 2 < ITERS) issue(it + 2);
        CP_COMMIT();
        const uint32_t st = sb + (it % STAGES) * STAGE_BYTES;
        compute_stage(st, st + A_BYTES, f, c);
    }

    float* Cp = (blockIdx.z == 0 ? Out : g_part) + (size_t)m0 * kD + n0;
#pragma unroll
    for (int mi = 0; mi < 4; ++mi)
#pragma unroll
        for (int nj = 0; nj < 4; ++nj) {
            const int r0 = f.wm + 16 * mi + f.g;
            const int cc = f.wn + 8 * nj + 2 * f.tig;
            *(float2*)(Cp + (size_t)r0 * kD + cc) = make_float2(c[mi][nj][0], c[mi][nj][1]);
            *(float2*)(Cp + (size_t)(r0 + 8) * kD + cc) = make_float2(c[mi][nj][2], c[mi][nj][3]);
        }
}

// Combine split-K halves: Out += g_part
__global__ __launch_bounds__(256)
void moe_add(float* __restrict__ Out) {
    const size_t i4 = ((size_t)blockIdx.x * 256 + threadIdx.x) * 4;
    const float4 a = *(const float4*)(Out + i4);
    const float4 b = *(const float4*)(g_part + i4);
    *(float4*)(Out + i4) = make_float4(a.x + b.x, a.y + b.y, a.z + b.z, a.w + b.w);
}

// ---------------------------------------------------------------------------
// kernel_launch
//   0: hidden_states fp32 [T,D]   1: routing_weights fp32 [T,E]
//   2: router_indices (unused)    3: gate_up_proj fp32 [E,D,2F]
//   4: down_proj fp32 [E,F,D]     out: fp32 [T,D]
// ---------------------------------------------------------------------------
extern "C" void kernel_launch(void* const* d_in, const int* in_sizes, int n_in,
                              void* d_out, int out_size)
{
    const float* X   = (const float*)d_in[0];
    const float* RW  = (const float*)d_in[1];
    const float* Wgu = (const float*)d_in[3];
    const float* Wdn = (const float*)d_in[4];
    float* Out = (float*)d_out;

    cudaFuncSetAttribute(moe_gemm1, cudaFuncAttributeMaxDynamicSharedMemorySize, SMEM_BYTES);
    cudaFuncSetAttribute(moe_gemm2, cudaFuncAttributeMaxDynamicSharedMemorySize, SMEM_BYTES);

    prep_X<<<(int)(((size_t)kT * kD / 8) / 256), 256>>>(X);                    // 2048
    prep_Wgu<<<(int)(((size_t)kE * kD * k2F / 8) / 256), 256>>>(Wgu);          // 49152
    prep_Wd<<<(int)(((size_t)kE * kF * kD / 8) / 256), 256>>>(Wdn);            // 24576

    moe_gemm1<<<dim3(kT / BM, k2F / BN, kE), NTHREADS, SMEM_BYTES>>>(RW);      // (16,12,32)

    moe_gemm2<<<dim3(kT / BM, kD / BN, 2), NTHREADS, SMEM_BYTES>>>(Out);       // (16,16,2)
    moe_add<<<(int)(((size_t)kT * kD / 4) / 256), 256>>>(Out);                 // 4096
}

// round 14
// speedup vs baseline: 1.0877x; 1.0389x over previous
#include <cuda_runtime.h>
#include <cuda_fp16.h>
#include <cstdint>

// ---------------------------------------------------------------------------
// Problem constants
// ---------------------------------------------------------------------------
constexpr int kE = 32, kD = 2048, kF = 768, kT = 2048;
constexpr int k2F = 2 * kF;                       // 1536

constexpr int BM = 128, BN = 128, BK = 64;        // fp16: BK=64 (4 k16-steps)
constexpr int STAGES = 3;
constexpr int NTHREADS = 256;                     // 8 warps, 2(m) x 4(n), warp 64x32

constexpr int A_BYTES = BM * BK * 2;              // 16384
constexpr int B_BYTES = BK * BN * 2;              // 16384
constexpr int STAGE_BYTES = A_BYTES + B_BYTES;    // 32768
constexpr int SMEM_BYTES = STAGES * STAGE_BYTES;  // 98304 -> 2 CTA/SM

constexpr int KSPLIT = 8;                         // GEMM2 split-K over experts

// Scratch (device globals; uint4 arrays for 16B alignment)
__device__ uint4 g_Xh    [(size_t)kT * kD / 8];        // X fp16
__device__ uint4 g_Wguh  [(size_t)kE * kD * k2F / 8];  // Wgu fp16, gate/up col-interleaved
__device__ uint4 g_Wdh   [(size_t)kE * kF * kD / 8];   // Wd fp16
__device__ uint4 g_gatedh[(size_t)kE * kT * kF / 8];   // rw*up*silu(gate), fp16
__device__ float g_part  [(size_t)KSPLIT * kT * kD];   // split-K partials (8 x 16.8MB)

// ---------------------------------------------------------------------------
// helpers
// ---------------------------------------------------------------------------
__device__ __forceinline__ uint32_t smem_u32(const void* p) {
    uint32_t a;
    asm("{ .reg .u64 t; cvta.to.shared.u64 t, %1; cvt.u32.u64 %0, t; }"
        : "=r"(a) : "l"(p));
    return a;
}
__device__ __forceinline__ void cp16(uint32_t saddr, const void* g) {
    asm volatile("cp.async.cg.shared.global [%0], [%1], 16;" :: "r"(saddr), "l"(g));
}
#define CP_COMMIT() asm volatile("cp.async.commit_group;" ::: "memory")
#define CP_WAIT1()  asm volatile("cp.async.wait_group 1;" ::: "memory")

__device__ __forceinline__ void ldsm4(uint32_t* r, uint32_t addr) {
    asm volatile("ldmatrix.sync.aligned.m8n8.x4.shared.b16 {%0,%1,%2,%3}, [%4];"
        : "=r"(r[0]), "=r"(r[1]), "=r"(r[2]), "=r"(r[3]) : "r"(addr));
}
__device__ __forceinline__ void ldsm4t(uint32_t* r, uint32_t addr) {
    asm volatile("ldmatrix.sync.aligned.m8n8.x4.trans.shared.b16 {%0,%1,%2,%3}, [%4];"
        : "=r"(r[0]), "=r"(r[1]), "=r"(r[2]), "=r"(r[3]) : "r"(addr));
}
__device__ __forceinline__ void mma16(float* c, const uint32_t* a, const uint32_t* b) {
    asm volatile(
        "mma.sync.aligned.m16n8k16.row.col.f32.f16.f16.f32 "
        "{%0,%1,%2,%3}, {%4,%5,%6,%7}, {%8,%9}, {%0,%1,%2,%3};"
        : "+f"(c[0]), "+f"(c[1]), "+f"(c[2]), "+f"(c[3])
        : "r"(a[0]), "r"(a[1]), "r"(a[2]), "r"(a[3]), "r"(b[0]), "r"(b[1]));
}

__device__ __forceinline__ uint32_t pack2(float x, float y) {
    __half2 h = __floats2half2_rn(x, y);
    return *reinterpret_cast<uint32_t*>(&h);
}

// ---------------------------------------------------------------------------
// Per-thread fragment addressing (precomputed outside K loop)
// A tile: [BM][64] halves, 128B rows, 16B-unit swizzle u^=(row&7).
// B tile: [BK][128] halves, 256B rows, swizzle per 128B half.
// ---------------------------------------------------------------------------
struct Frag {
    int aRow[4];
    int aMask[4];
    int hi;
    int bOff[2];
    int g, tig, wm, wn;
};

__device__ __forceinline__ Frag make_frag(int tid) {
    Frag f;
    const int l = tid & 31, wid = tid >> 5;
    f.wm = (wid >> 2) * 64;
    f.wn = (wid & 3) * 32;
    f.g = l >> 2; f.tig = l & 3;
    f.hi = l >> 4;
    const int low8 = l & 7, seg8 = (l >> 3) & 1;
#pragma unroll
    for (int mi = 0; mi < 4; ++mi) {
        const int rA = f.wm + 16 * mi + low8 + 8 * seg8;
        f.aRow[mi] = rA * 128;
        f.aMask[mi] = rA & 7;
    }
#pragma unroll
    for (int p = 0; p < 2; ++p) {
        const int uB = (f.wn >> 3) + 2 * p + f.hi;
        f.bOff[p] = (l & 15) * 256 + ((uB >> 3) << 7) + ((((uB & 7) ^ low8)) << 4);
    }
    return f;
}

// Software-pipelined stage (k-step fragments prefetched one step ahead).
__device__ __forceinline__ void compute_stage(uint32_t As, uint32_t Bs,
                                              const Frag& f, float c[4][4][4]) {
    uint32_t a[2][4][4], rb[2][2][4];
#pragma unroll
    for (int mi = 0; mi < 4; ++mi)
        ldsm4(a[0][mi], As + f.aRow[mi] + ((f.hi ^ f.aMask[mi]) << 4));
#pragma unroll
    for (int p = 0; p < 2; ++p)
        ldsm4t(rb[0][p], Bs + f.bOff[p]);

#pragma unroll
    for (int ks = 0; ks < 4; ++ks) {
        const int cur = ks & 1, nxt = cur ^ 1;
        if (ks < 3) {
            const int kkU = 2 * (ks + 1);
#pragma unroll
            for (int mi = 0; mi < 4; ++mi)
                ldsm4(a[nxt][mi], As + f.aRow[mi] + (((kkU + f.hi) ^ f.aMask[mi]) << 4));
#pragma unroll
            for (int p = 0; p < 2; ++p)
                ldsm4t(rb[nxt][p], Bs + (16 * (ks + 1)) * 256 + f.bOff[p]);
        }
#pragma unroll
        for (int mi = 0; mi < 4; ++mi)
#pragma unroll
            for (int p = 0; p < 2; ++p) {
                mma16(c[mi][2 * p + 0], a[cur][mi], &rb[cur][p][0]);
                mma16(c[mi][2 * p + 1], a[cur][mi], &rb[cur][p][2]);
            }
    }
}

// cp.async destination offsets (byte), swizzled
__device__ __forceinline__ uint32_t a_dst(int row, int u) {        // u 0..7
    return (uint32_t)(row * 128 + ((u ^ (row & 7)) << 4));
}
__device__ __forceinline__ uint32_t b_dst(int row, int u) {        // u 0..15
    return (uint32_t)(row * 256 + ((u >> 3) << 7) + ((((u & 7) ^ (row & 7))) << 4));
}

// ---------------------------------------------------------------------------
// Pre-pass kernels
// ---------------------------------------------------------------------------
__device__ __forceinline__ void conv8(const float* src, uint4* dst) {
    const float4 a = *(const float4*)(src);
    const float4 b = *(const float4*)(src + 4);
    uint4 o;
    o.x = pack2(a.x, a.y); o.y = pack2(a.z, a.w);
    o.z = pack2(b.x, b.y); o.w = pack2(b.z, b.w);
    *dst = o;
}
__global__ __launch_bounds__(256) void prep_X(const float* __restrict__ X) {
    const size_t i = (size_t)blockIdx.x * 256 + threadIdx.x;
    conv8(X + i * 8, g_Xh + i);
}
// Wgu: interleave gate/up columns. Output col 2j = orig col j (gate),
// output col 2j+1 = orig col j+kF (up).
__global__ __launch_bounds__(256) void prep_Wgu(const float* __restrict__ W) {
    const size_t i = (size_t)blockIdx.x * 256 + threadIdx.x;  // over E*D*2F/8
    constexpr int NG = k2F / 8;                               // 192 groups/row
    const int grp = (int)(i % NG);
    const size_t row = i / NG;
    const float* src = W + row * k2F;
    const int j0 = grp * 4;
    const float4 gt = *(const float4*)(src + j0);
    const float4 up = *(const float4*)(src + kF + j0);
    uint4 o;
    o.x = pack2(gt.x, up.x); o.y = pack2(gt.y, up.y);
    o.z = pack2(gt.z, up.z); o.w = pack2(gt.w, up.w);
    g_Wguh[i] = o;
}
__global__ __launch_bounds__(256) void prep_Wd(const float* __restrict__ W) {
    const size_t i = (size_t)blockIdx.x * 256 + threadIdx.x;
    conv8(W + i * 8, g_Wdh + i);
}

// ---------------------------------------------------------------------------
// GEMM1 (fused): C = Xh @ Wguh (gate/up interleaved cols); epilogue computes
// fp16(rw*up*silu(gate)), stages through smem, stores coalesced 16B chunks.
// grid (16, 12, 32), 256 threads, 32 K-iters of BK=64.
// ---------------------------------------------------------------------------
constexpr int EP_LD = 72;   // halves per staging row (144B; pad kills bank alias)

__global__ __launch_bounds__(NTHREADS, 2)
void moe_gemm1(const float* __restrict__ RW) {
    extern __shared__ char smem[];
    const int tid = threadIdx.x;
    const int m0 = blockIdx.x * BM, n0 = blockIdx.y * BN, e = blockIdx.z;
    const uint32_t sb = smem_u32(smem);

    const __half* Xh = (const __half*)g_Xh;
    const __half* We = (const __half*)g_Wguh + (size_t)e * kD * k2F;

    const int arow = tid >> 1, au = (tid & 1) * 4;
    const int brow = tid >> 2, bu = (tid & 3) * 4;
    const __half* gA = Xh + (size_t)(m0 + arow) * kD + au * 8;
    const __half* gB = We + (size_t)brow * k2F + n0 + bu * 8;

    uint32_t aD[4], bD[4];
#pragma unroll
    for (int q = 0; q < 4; ++q) {
        aD[q] = a_dst(arow, au + q);
        bD[q] = b_dst(brow, bu + q);
    }

    const Frag f = make_frag(tid);
    float c[4][4][4];
#pragma unroll
    for (int i = 0; i < 4; ++i)
#pragma unroll
        for (int j = 0; j < 4; ++j)
#pragma unroll
            for (int q = 0; q < 4; ++q) c[i][j][q] = 0.0f;

    constexpr int ITERS = kD / BK;   // 32

    auto issue = [&](int it) {
        const uint32_t st = sb + (it % STAGES) * STAGE_BYTES;
        const int k0 = it * BK;
#pragma unroll
        for (int q = 0; q < 4; ++q)
            cp16(st + aD[q], gA + k0 + q * 8);
#pragma unroll
        for (int q = 0; q < 4; ++q)
            cp16(st + A_BYTES + bD[q], gB + (size_t)k0 * k2F + q * 8);
    };

    issue(0); CP_COMMIT();
    issue(1); CP_COMMIT();

    for (int it = 0; it < ITERS; ++it) {
        CP_WAIT1();
        __syncthreads();
        if (it + 2 < ITERS) issue(it + 2);
        CP_COMMIT();
        const uint32_t st = sb + (it % STAGES) * STAGE_BYTES;
        compute_stage(st, st + A_BYTES, f, c);
    }

    // ---- Fused epilogue, smem-staged for coalesced stores ----
    __syncthreads();
    __half* s_ep = (__half*)smem;            // [128 rows][EP_LD halves]
#pragma unroll
    for (int mi = 0; mi < 4; ++mi) {
        const int row0 = f.wm + 16 * mi + f.g;
        const int row1 = row0 + 8;
        const float rw0 = RW[(size_t)(m0 + row0) * kE + e];
        const float rw1 = RW[(size_t)(m0 + row1) * kE + e];
#pragma unroll
        for (int nj = 0; nj < 4; ++nj) {
            const int fl = (f.wn >> 1) + 4 * nj + f.tig;
            const float gt0 = c[mi][nj][0], up0 = c[mi][nj][1];
            const float gt1 = c[mi][nj][2], up1 = c[mi][nj][3];
            s_ep[row0 * EP_LD + fl] =
                __float2half_rn(rw0 * up0 * (gt0 / (1.0f + __expf(-gt0))));
            s_ep[row1 * EP_LD + fl] =
                __float2half_rn(rw1 * up1 * (gt1 / (1.0f + __expf(-gt1))));
        }
    }
    __syncthreads();

    const int erow = tid >> 1, eseg = (tid & 1) * 32;
    const int f0 = n0 >> 1;
    const uint4* src = (const uint4*)(s_ep + erow * EP_LD + eseg);
    uint4* dst = (uint4*)((__half*)g_gatedh +
                          ((size_t)e * kT + m0 + erow) * kF + f0 + eseg);
#pragma unroll
    for (int q = 0; q < 4; ++q) dst[q] = src[q];
}

// ---------------------------------------------------------------------------
// GEMM2 (split-K x8 over experts): z handles experts [4z, 4z+4) -> g_part[z].
// grid (16, 16, 8), 256 threads, 48 K-iters of BK=64.
// ---------------------------------------------------------------------------
__global__ __launch_bounds__(NTHREADS, 2)
void moe_gemm2() {
    extern __shared__ char smem[];
    const int tid = threadIdx.x;
    const int m0 = blockIdx.x * BM, n0 = blockIdx.y * BN;
    const int ez = blockIdx.z * (kE / KSPLIT);
    const uint32_t sb = smem_u32(smem);

    const __half* Ah = (const __half*)g_gatedh;
    const __half* Wh = (const __half*)g_Wdh;

    const int arow = tid >> 1, au = (tid & 1) * 4;
    const int brow = tid >> 2, bu = (tid & 3) * 4;

    uint32_t aD[4], bD[4];
#pragma unroll
    for (int q = 0; q < 4; ++q) {
        aD[q] = a_dst(arow, au + q);
        bD[q] = b_dst(brow, bu + q);
    }

    const Frag f = make_frag(tid);
    float c[4][4][4];
#pragma unroll
    for (int i = 0; i < 4; ++i)
#pragma unroll
        for (int j = 0; j < 4; ++j)
#pragma unroll
            for (int q = 0; q < 4; ++q) c[i][j][q] = 0.0f;

    constexpr int IPEX  = kF / BK;                       // 12
    constexpr int ITERS = (kE / KSPLIT) * IPEX;          // 48

    auto issue = [&](int it) {
        const uint32_t st = sb + (it % STAGES) * STAGE_BYTES;
        const int e   = ez + it / IPEX;
        const int kin = (it % IPEX) * BK;
        const __half* gA = Ah + ((size_t)e * kT + m0 + arow) * kF + kin + au * 8;
        const __half* gB = Wh + ((size_t)e * kF + kin + brow) * kD + n0 + bu * 8;
#pragma unroll
        for (int q = 0; q < 4; ++q)
            cp16(st + aD[q], gA + q * 8);
#pragma unroll
        for (int q = 0; q < 4; ++q)
            cp16(st + A_BYTES + bD[q], gB + q * 8);
    };

    issue(0); CP_COMMIT();
    issue(1); CP_COMMIT();

    for (int it = 0; it < ITERS; ++it) {
        CP_WAIT1();
        __syncthreads();
        if (it + 2 < ITERS) issue(it + 2);
        CP_COMMIT();
        const uint32_t st = sb + (it % STAGES) * STAGE_BYTES;
        compute_stage(st, st + A_BYTES, f, c);
    }

    float* Cp = g_part + (size_t)blockIdx.z * kT * kD + (size_t)m0 * kD + n0;
#pragma unroll
    for (int mi = 0; mi < 4; ++mi)
#pragma unroll
        for (int nj = 0; nj < 4; ++nj) {
            const int r0 = f.wm + 16 * mi + f.g;
            const int cc = f.wn + 8 * nj + 2 * f.tig;
            *(float2*)(Cp + (size_t)r0 * kD + cc) = make_float2(c[mi][nj][0], c[mi][nj][1]);
            *(float2*)(Cp + (size_t)(r0 + 8) * kD + cc) = make_float2(c[mi][nj][2], c[mi][nj][3]);
        }
}

// Combine split-K partials: Out = sum_z g_part[z]
__global__ __launch_bounds__(256)
void moe_add(float* __restrict__ Out) {
    const size_t i4 = ((size_t)blockIdx.x * 256 + threadIdx.x) * 4;
    float4 s = *(const float4*)(g_part + i4);
#pragma unroll
    for (int z = 1; z < KSPLIT; ++z) {
        const float4 b = *(const float4*)(g_part + (size_t)z * kT * kD + i4);
        s.x += b.x; s.y += b.y; s.z += b.z; s.w += b.w;
    }
    *(float4*)(Out + i4) = s;
}

// ---------------------------------------------------------------------------
// kernel_launch
//   0: hidden_states fp32 [T,D]   1: routing_weights fp32 [T,E]
//   2: router_indices (unused)    3: gate_up_proj fp32 [E,D,2F]
//   4: down_proj fp32 [E,F,D]     out: fp32 [T,D]
// ---------------------------------------------------------------------------
extern "C" void kernel_launch(void* const* d_in, const int* in_sizes, int n_in,
                              void* d_out, int out_size)
{
    const float* X   = (const float*)d_in[0];
    const float* RW  = (const float*)d_in[1];
    const float* Wgu = (const float*)d_in[3];
    const float* Wdn = (const float*)d_in[4];
    float* Out = (float*)d_out;

    cudaFuncSetAttribute(moe_gemm1, cudaFuncAttributeMaxDynamicSharedMemorySize, SMEM_BYTES);
    cudaFuncSetAttribute(moe_gemm2, cudaFuncAttributeMaxDynamicSharedMemorySize, SMEM_BYTES);

    prep_X<<<(int)(((size_t)kT * kD / 8) / 256), 256>>>(X);                    // 2048
    prep_Wgu<<<(int)(((size_t)kE * kD * k2F / 8) / 256), 256>>>(Wgu);          // 49152
    prep_Wd<<<(int)(((size_t)kE * kF * kD / 8) / 256), 256>>>(Wdn);            // 24576

    moe_gemm1<<<dim3(kT / BM, k2F / BN, kE), NTHREADS, SMEM_BYTES>>>(RW);      // (16,12,32)

    moe_gemm2<<<dim3(kT / BM, kD / BN, KSPLIT), NTHREADS, SMEM_BYTES>>>();     // (16,16,8)
    moe_add<<<(int)(((size_t)kT * kD / 4) / 256), 256>>>(Out);                 // 4096
}